// round 10
// baseline (speedup 1.0000x reference)
#include <cuda_runtime.h>
#include <cuda_fp16.h>
#include <cstdint>

#define BATCH 2
#define CCH 128
#define ICH 16
#define NP 9216
#define QB 64                // queries per CTA
#define KT 128               // keys per tile
#define NT (NP / KT)         // 72
#define NQB (NP / QB)        // 144
#define LOG2E 1.4426950408889634f

// smem byte offsets (K stride 80B/key; V stride 272B/row)
#define K0_OFF 0
#define K1_OFF 10240
#define V0_OFF 20480
#define V1_OFF 29184
#define WO_OFF 37888
#define BO_OFF 46080
#define SO_OFF 46592
#define SMEM_BYTES 50944
// cross-warp partial area aliases K0 tile buffer after the mainloop

typedef unsigned int u32;

__device__ __align__(16) u32 g_q2[BATCH * NP * 16];            // per query: 8 u32 fp16-hi pairs, 8 lo
__device__ __align__(16) u32 g_k2[BATCH * NP * 16];            // same for K
__device__ __align__(16) unsigned short g_vt[BATCH * 32 * NP]; // rows 0-15 Vh (bf16), 16-31 Vl

static __device__ __forceinline__ float ex2f(float x) {
    float r; asm("ex2.approx.f32 %0, %1;" : "=f"(r) : "f"(x)); return r;
}
static __device__ __forceinline__ u32 pack_bf16(float a, float b) {
    return __byte_perm(__float_as_uint(a), __float_as_uint(b), 0x7632);
}
static __device__ __forceinline__ float lo_of(float a) {
    return a - __uint_as_float(__float_as_uint(a) & 0xFFFF0000u);
}
static __device__ __forceinline__ u32 pack_f16(__half a, __half b) {
    return (u32)__half_as_ushort(a) | ((u32)__half_as_ushort(b) << 16);
}
static __device__ __forceinline__ void cpasync16(void* s, const void* g) {
    u32 a = (u32)__cvta_generic_to_shared(s);
    asm volatile("cp.async.cg.shared.global [%0], [%1], 16;" :: "r"(a), "l"(g));
}
#define CP_COMMIT() asm volatile("cp.async.commit_group;" ::: "memory")

#define MMA_F16(d, a, b0, b1) \
    asm volatile("mma.sync.aligned.m16n8k16.row.col.f32.f16.f16.f32 " \
        "{%0,%1,%2,%3},{%4,%5,%6,%7},{%8,%9},{%0,%1,%2,%3};" \
        : "+f"((d)[0]), "+f"((d)[1]), "+f"((d)[2]), "+f"((d)[3]) \
        : "r"((a)[0]), "r"((a)[1]), "r"((a)[2]), "r"((a)[3]), "r"(b0), "r"(b1))

#define MMA_BF16(d, a, b0, b1) \
    asm volatile("mma.sync.aligned.m16n8k16.row.col.f32.bf16.bf16.f32 " \
        "{%0,%1,%2,%3},{%4,%5,%6,%7},{%8,%9},{%0,%1,%2,%3};" \
        : "+f"((d)[0]), "+f"((d)[1]), "+f"((d)[2]), "+f"((d)[3]) \
        : "r"((a)[0]), "r"((a)[1]), "r"((a)[2]), "r"((a)[3]), "r"(b0), "r"(b1))

// ============================================================================
// Kernel 1: qkv projections -> fp16 hi/lo Q,K ; bf16 hi/lo V (transposed)
// ============================================================================
__global__ void __launch_bounds__(256) qkv_kernel(
    const float* __restrict__ x,
    const float* __restrict__ Wq, const float* __restrict__ bq,
    const float* __restrict__ Wk, const float* __restrict__ bk,
    const float* __restrict__ Wv, const float* __restrict__ bv)
{
    __shared__ float sWq[ICH * CCH], sWk[ICH * CCH], sWv[ICH * CCH];
    __shared__ float sb[3 * ICH];
    for (int i = threadIdx.x; i < ICH * CCH; i += 256) {
        sWq[i] = Wq[i]; sWk[i] = Wk[i]; sWv[i] = Wv[i];
    }
    if (threadIdx.x < ICH)            sb[threadIdx.x] = bq[threadIdx.x];
    else if (threadIdx.x < 2 * ICH)   sb[threadIdx.x] = bk[threadIdx.x - ICH];
    else if (threadIdx.x < 3 * ICH)   sb[threadIdx.x] = bv[threadIdx.x - 2 * ICH];
    __syncthreads();

    int gid = blockIdx.x * 256 + threadIdx.x;
    int b = gid / NP, n = gid % NP;
    const float* xb = x + (size_t)b * CCH * NP + n;

    float aq[ICH], ak[ICH], av[ICH];
    #pragma unroll
    for (int i = 0; i < ICH; i++) { aq[i] = 0.f; ak[i] = 0.f; av[i] = 0.f; }

    for (int c = 0; c < CCH; c += 4) {
        float x0 = xb[(size_t)(c + 0) * NP];
        float x1 = xb[(size_t)(c + 1) * NP];
        float x2 = xb[(size_t)(c + 2) * NP];
        float x3 = xb[(size_t)(c + 3) * NP];
        #pragma unroll
        for (int i = 0; i < ICH; i++) {
            float4 wq = *(const float4*)&sWq[i * CCH + c];
            aq[i] = fmaf(wq.x, x0, fmaf(wq.y, x1, fmaf(wq.z, x2, fmaf(wq.w, x3, aq[i]))));
            float4 wk = *(const float4*)&sWk[i * CCH + c];
            ak[i] = fmaf(wk.x, x0, fmaf(wk.y, x1, fmaf(wk.z, x2, fmaf(wk.w, x3, ak[i]))));
            float4 wv = *(const float4*)&sWv[i * CCH + c];
            av[i] = fmaf(wv.x, x0, fmaf(wv.y, x1, fmaf(wv.z, x2, fmaf(wv.w, x3, av[i]))));
        }
    }

    float qf[ICH], kf[ICH];
    #pragma unroll
    for (int i = 0; i < ICH; i++) {
        qf[i] = (aq[i] + sb[i]) * LOG2E;
        kf[i] = ak[i] + sb[ICH + i];
    }
    u32* qo = g_q2 + (size_t)gid * 16;
    u32* ko = g_k2 + (size_t)gid * 16;
    #pragma unroll
    for (int j = 0; j < 8; j++) {
        __half qh0 = __float2half_rn(qf[2 * j]),     qh1 = __float2half_rn(qf[2 * j + 1]);
        float  qlo0 = qf[2 * j] - __half2float(qh0), qlo1 = qf[2 * j + 1] - __half2float(qh1);
        qo[j]     = pack_f16(qh0, qh1);
        qo[8 + j] = pack_f16(__float2half_rn(qlo0), __float2half_rn(qlo1));
        __half kh0 = __float2half_rn(kf[2 * j]),     kh1 = __float2half_rn(kf[2 * j + 1]);
        float  klo0 = kf[2 * j] - __half2float(kh0), klo1 = kf[2 * j + 1] - __half2float(kh1);
        ko[j]     = pack_f16(kh0, kh1);
        ko[8 + j] = pack_f16(__float2half_rn(klo0), __float2half_rn(klo1));
    }
    unsigned short* vt = g_vt + (size_t)b * 32 * NP + n;
    #pragma unroll
    for (int i = 0; i < ICH; i++) {
        float vv = av[i] + sb[2 * ICH + i];
        vt[(size_t)i * NP]        = (unsigned short)(__float_as_uint(vv) >> 16);
        vt[(size_t)(16 + i) * NP] = (unsigned short)(__float_as_uint(lo_of(vv)) >> 16);
    }
}

// ---------------- tile loaders (256 threads) ----------------
static __device__ __forceinline__ void load_k_tile(const char* gk, char* dst, int t, int tid) {
    const char* src = gk + (size_t)t * KT * 64;
    #pragma unroll
    for (int r = 0; r < 2; r++) {
        int idx = r * 256 + tid;
        int key = idx >> 2, c = idx & 3;
        cpasync16(dst + key * 80 + c * 16, src + key * 64 + c * 16);
    }
}
static __device__ __forceinline__ void load_v_tile(const char* gv, char* dst, int t, int tid) {
    #pragma unroll
    for (int r = 0; r < 2; r++) {
        int idx = r * 256 + tid;
        int row = idx >> 4, c = idx & 15;
        cpasync16(dst + row * 272 + c * 16, gv + (size_t)row * (NP * 2) + t * 256 + c * 16);
    }
}

// ============================================================================
// Kernel 2: HMMA flash attention, key-split across warp halves, deep ILP
// ============================================================================
__global__ void __launch_bounds__(256, 2) attn_kernel(
    const float* __restrict__ x, const float* __restrict__ Wo,
    const float* __restrict__ bo, const float* __restrict__ gamma,
    float* __restrict__ y)
{
    extern __shared__ char smc[];
    const int tid = threadIdx.x;
    const int w = tid >> 5, lane = tid & 31;
    const int wq = w & 3;            // query group (16 queries)
    const int wk = w >> 2;           // key half of each tile
    const int gr = lane >> 2, tg = lane & 3;
    const int b  = blockIdx.x / NQB;
    const int q0 = (blockIdx.x % NQB) * QB;

    float* sWo = (float*)(smc + WO_OFF);
    float* sbo = (float*)(smc + BO_OFF);
    float* sO  = (float*)(smc + SO_OFF);
    for (int i = tid; i < ICH * CCH; i += 256) sWo[i] = Wo[i];
    if (tid < CCH) sbo[tid] = bo[tid];

    // Q fragments for this warp's 16 queries (rows wq*16 + gr, +8)
    const u32* qp  = g_q2 + (size_t)(b * NP + q0 + wq * 16 + gr) * 16;
    const u32* qp8 = qp + 8 * 16;
    u32 qh[4], ql[4];
    qh[0] = qp[tg];     qh[1] = qp8[tg];     qh[2] = qp[tg + 4];  qh[3] = qp8[tg + 4];
    ql[0] = qp[8 + tg]; ql[1] = qp8[8 + tg]; ql[2] = qp[12 + tg]; ql[3] = qp8[12 + tg];

    // AV accumulators: oA split by chunk parity (breaks cross-chunk RAW chain)
    float oA0[2][4] = {}, oA1[2][4] = {}, oB[2][4] = {}, oC[2][4] = {};
    float dn0 = 0.f, dn1 = 0.f;

    const char* gk = (const char*)(g_k2 + (size_t)b * NP * 16);
    const char* gv = (const char*)(g_vt + (size_t)b * 32 * NP);

    load_k_tile(gk, smc + K0_OFF, 0, tid);
    load_v_tile(gv, smc + V0_OFF, 0, tid);
    CP_COMMIT();

    int buf = 0;
    for (int t = 0; t < NT; t++) {
        if (t + 1 < NT) {
            load_k_tile(gk, smc + (buf ? K0_OFF : K1_OFF), t + 1, tid);
            load_v_tile(gv, smc + (buf ? V0_OFF : V1_OFF), t + 1, tid);
            CP_COMMIT();
            asm volatile("cp.async.wait_group 1;" ::: "memory");
        } else {
            asm volatile("cp.async.wait_group 0;" ::: "memory");
        }
        __syncthreads();

        const char* kb = smc + (buf ? K1_OFF : K0_OFF);
        const char* vb = smc + (buf ? V1_OFF : V0_OFF);

        #pragma unroll
        for (int c2 = 0; c2 < 4; c2++) {
            const int ck = wk * 4 + c2;   // this warp's key chunk (16 keys)
            // --- QK: two independent accumulator streams per key group ---
            float sa0[4] = {0.f,0.f,0.f,0.f}, sb0[4] = {0.f,0.f,0.f,0.f};
            float sa1[4] = {0.f,0.f,0.f,0.f}, sb1[4] = {0.f,0.f,0.f,0.f};
            const char* ka = kb + (ck * 16 + gr) * 80 + tg * 4;
            {
                u32 b0 = *(const u32*)ka,        b1 = *(const u32*)(ka + 16);
                u32 c0 = *(const u32*)(ka + 32), c1 = *(const u32*)(ka + 48);
                MMA_F16(sa0, qh, b0, b1);
                MMA_F16(sb0, qh, c0, c1);
                MMA_F16(sa0, ql, b0, b1);
            }
            {
                const char* ka1 = ka + 8 * 80;
                u32 b0 = *(const u32*)ka1,        b1 = *(const u32*)(ka1 + 16);
                u32 c0 = *(const u32*)(ka1 + 32), c1 = *(const u32*)(ka1 + 48);
                MMA_F16(sa1, qh, b0, b1);
                MMA_F16(sb1, qh, c0, c1);
                MMA_F16(sa1, ql, b0, b1);
            }
            float p00 = ex2f(sa0[0] + sb0[0]), p01 = ex2f(sa0[1] + sb0[1]);
            float p02 = ex2f(sa0[2] + sb0[2]), p03 = ex2f(sa0[3] + sb0[3]);
            float p10 = ex2f(sa1[0] + sb1[0]), p11 = ex2f(sa1[1] + sb1[1]);
            float p12 = ex2f(sa1[2] + sb1[2]), p13 = ex2f(sa1[3] + sb1[3]);
            dn0 += p00 + p01 + p10 + p11;
            dn1 += p02 + p03 + p12 + p13;
            u32 pah[4], pal[4];
            pah[0] = pack_bf16(p00, p01); pah[1] = pack_bf16(p02, p03);
            pah[2] = pack_bf16(p10, p11); pah[3] = pack_bf16(p12, p13);
            pal[0] = pack_bf16(lo_of(p00), lo_of(p01)); pal[1] = pack_bf16(lo_of(p02), lo_of(p03));
            pal[2] = pack_bf16(lo_of(p10), lo_of(p11)); pal[3] = pack_bf16(lo_of(p12), lo_of(p13));

            float (*oAp)[4] = (c2 & 1) ? oA1 : oA0;
            #pragma unroll
            for (int cb = 0; cb < 2; cb++) {
                const char* va = vb + (cb * 8 + gr) * 272 + ck * 32 + tg * 4;
                u32 vh0 = *(const u32*)va,              vh1 = *(const u32*)(va + 16);
                u32 vl0 = *(const u32*)(va + 16 * 272), vl1 = *(const u32*)(va + 16 * 272 + 16);
                MMA_BF16(oAp[cb], pah, vh0, vh1);
                MMA_BF16(oB[cb],  pal, vh0, vh1);
                MMA_BF16(oC[cb],  pah, vl0, vl1);
            }
        }
        __syncthreads();
        buf ^= 1;
    }

    // combine accumulator streams
    float ro[2][4];
    #pragma unroll
    for (int cb = 0; cb < 2; cb++)
        #pragma unroll
        for (int i = 0; i < 4; i++)
            ro[cb][i] = (oA0[cb][i] + oA1[cb][i]) + (oB[cb][i] + oC[cb][i]);

    // quad-reduce denominators (lanes tg=0..3 hold disjoint key-column subsets)
    dn0 += __shfl_xor_sync(0xFFFFFFFFu, dn0, 1);
    dn0 += __shfl_xor_sync(0xFFFFFFFFu, dn0, 2);
    dn1 += __shfl_xor_sync(0xFFFFFFFFu, dn1, 1);
    dn1 += __shfl_xor_sync(0xFFFFFFFFu, dn1, 2);

    // cross-warp-half reduction via smem (aliases dead K0 tile buffer)
    float* part = (float*)(smc + K0_OFF);   // [64][18]: 16 out cols + dn
    const int r0 = wq * 16 + gr, r1 = r0 + 8;
    if (wk == 1) {
        #pragma unroll
        for (int cb = 0; cb < 2; cb++) {
            int col = cb * 8 + tg * 2;
            part[r0 * 18 + col]     = ro[cb][0];
            part[r0 * 18 + col + 1] = ro[cb][1];
            part[r1 * 18 + col]     = ro[cb][2];
            part[r1 * 18 + col + 1] = ro[cb][3];
        }
        if (tg == 0) { part[r0 * 18 + 16] = dn0; part[r1 * 18 + 16] = dn1; }
    }
    __syncthreads();
    if (wk == 0) {
        float id0 = 1.0f / (dn0 + part[r0 * 18 + 16]);
        float id1 = 1.0f / (dn1 + part[r1 * 18 + 16]);
        #pragma unroll
        for (int cb = 0; cb < 2; cb++) {
            int col = cb * 8 + tg * 2;
            sO[r0 * 17 + col]     = (ro[cb][0] + part[r0 * 18 + col])     * id0;
            sO[r0 * 17 + col + 1] = (ro[cb][1] + part[r0 * 18 + col + 1]) * id0;
            sO[r1 * 17 + col]     = (ro[cb][2] + part[r1 * 18 + col])     * id1;
            sO[r1 * 17 + col + 1] = (ro[cb][3] + part[r1 * 18 + col + 1]) * id1;
        }
    }
    __syncthreads();

    // epilogue: y = gamma * (Wo @ O + bo) + x
    const float gam = gamma[0];
    for (int idx = tid; idx < CCH * QB; idx += 256) {
        int c = idx >> 6, q = idx & 63;
        const float* wr = sWo + c * ICH;
        const float* ov = sO + q * 17;
        float acc = 0.f;
        #pragma unroll
        for (int i = 0; i < ICH; i++) acc = fmaf(wr[i], ov[i], acc);
        size_t gi = ((size_t)(b * CCH + c)) * NP + (q0 + q);
        y[gi] = gam * (acc + sbo[c]) + x[gi];
    }
}

extern "C" void kernel_launch(void* const* d_in, const int* in_sizes, int n_in,
                              void* d_out, int out_size) {
    const float* x     = (const float*)d_in[0];
    const float* Wq    = (const float*)d_in[1];
    const float* bq    = (const float*)d_in[2];
    const float* Wk    = (const float*)d_in[3];
    const float* bk    = (const float*)d_in[4];
    const float* Wv    = (const float*)d_in[5];
    const float* bv    = (const float*)d_in[6];
    const float* Wo    = (const float*)d_in[7];
    const float* bo    = (const float*)d_in[8];
    const float* gamma = (const float*)d_in[9];
    float* y = (float*)d_out;

    cudaFuncSetAttribute(attn_kernel, cudaFuncAttributeMaxDynamicSharedMemorySize, SMEM_BYTES);

    qkv_kernel<<<(BATCH * NP) / 256, 256>>>(x, Wq, bq, Wk, bk, Wv, bv);
    attn_kernel<<<BATCH * NQB, 256, SMEM_BYTES>>>(x, Wo, bo, gamma, y);
}

// round 11
// speedup vs baseline: 1.1491x; 1.1491x over previous
#include <cuda_runtime.h>
#include <cuda_fp16.h>
#include <cstdint>

#define BATCH 2
#define CCH 128
#define ICH 16
#define NP 9216
#define QB 64                // queries per CTA
#define KT 128               // keys per tile
#define NT (NP / KT)         // 72
#define NQB (NP / QB)        // 144
#define LOG2E 1.4426950408889634f

// smem byte offsets: K stride 80B/key (LDS.128-friendly), V stride 288B/row (LDS.64)
#define K0_OFF 0
#define K1_OFF 10240
#define V0_OFF 20480
#define V1_OFF 29696
#define WO_OFF 38912
#define BO_OFF 47104
#define SO_OFF 47616
#define SMEM_BYTES 51968
// cross-warp partial area aliases K0 tile buffer after the mainloop: [64][18]

typedef unsigned int u32;

__device__ __align__(16) u32 g_q2[BATCH * NP * 16];            // per query: 8 fp16-hi pair words, 8 lo
__device__ __align__(16) u32 g_k2[BATCH * NP * 16];            // per key: tg-grouped {hi[tg],hi[tg+4],lo[tg],lo[tg+4]}
__device__ __align__(16) unsigned short g_vt[BATCH * 32 * NP]; // rows 0-15 Vh (bf16), 16-31 Vl; keys pair-permuted per 16

static __device__ __forceinline__ float ex2f(float x) {
    float r; asm("ex2.approx.f32 %0, %1;" : "=f"(r) : "f"(x)); return r;
}
// pack two floats to bf16x2 (p0 -> low half), round-to-nearest
static __device__ __forceinline__ u32 pack_bf16_rn(float p0, float p1) {
    u32 d; asm("cvt.rn.satfinite.bf16x2.f32 %0, %1, %2;" : "=r"(d) : "f"(p1), "f"(p0)); return d;
}
static __device__ __forceinline__ float lo_of(float a) {
    return a - __uint_as_float(__float_as_uint(a) & 0xFFFF0000u);
}
static __device__ __forceinline__ u32 pack_f16(__half a, __half b) {
    return (u32)__half_as_ushort(a) | ((u32)__half_as_ushort(b) << 16);
}
static __device__ __forceinline__ void cpasync16(void* s, const void* g) {
    u32 a = (u32)__cvta_generic_to_shared(s);
    asm volatile("cp.async.cg.shared.global [%0], [%1], 16;" :: "r"(a), "l"(g));
}
#define CP_COMMIT() asm volatile("cp.async.commit_group;" ::: "memory")

#define MMA_F16(d, a, b0, b1) \
    asm volatile("mma.sync.aligned.m16n8k16.row.col.f32.f16.f16.f32 " \
        "{%0,%1,%2,%3},{%4,%5,%6,%7},{%8,%9},{%0,%1,%2,%3};" \
        : "+f"((d)[0]), "+f"((d)[1]), "+f"((d)[2]), "+f"((d)[3]) \
        : "r"((a)[0]), "r"((a)[1]), "r"((a)[2]), "r"((a)[3]), "r"(b0), "r"(b1))

#define MMA_BF16(d, a, b0, b1) \
    asm volatile("mma.sync.aligned.m16n8k16.row.col.f32.bf16.bf16.f32 " \
        "{%0,%1,%2,%3},{%4,%5,%6,%7},{%8,%9},{%0,%1,%2,%3};" \
        : "+f"((d)[0]), "+f"((d)[1]), "+f"((d)[2]), "+f"((d)[3]) \
        : "r"((a)[0]), "r"((a)[1]), "r"((a)[2]), "r"((a)[3]), "r"(b0), "r"(b1))

// ============================================================================
// Kernel 1: qkv projections -> fp16 hi/lo Q,K ; bf16 hi/lo V (transposed)
// ============================================================================
__global__ void __launch_bounds__(256) qkv_kernel(
    const float* __restrict__ x,
    const float* __restrict__ Wq, const float* __restrict__ bq,
    const float* __restrict__ Wk, const float* __restrict__ bk,
    const float* __restrict__ Wv, const float* __restrict__ bv)
{
    __shared__ float sWq[ICH * CCH], sWk[ICH * CCH], sWv[ICH * CCH];
    __shared__ float sb[3 * ICH];
    for (int i = threadIdx.x; i < ICH * CCH; i += 256) {
        sWq[i] = Wq[i]; sWk[i] = Wk[i]; sWv[i] = Wv[i];
    }
    if (threadIdx.x < ICH)            sb[threadIdx.x] = bq[threadIdx.x];
    else if (threadIdx.x < 2 * ICH)   sb[threadIdx.x] = bk[threadIdx.x - ICH];
    else if (threadIdx.x < 3 * ICH)   sb[threadIdx.x] = bv[threadIdx.x - 2 * ICH];
    __syncthreads();

    int gid = blockIdx.x * 256 + threadIdx.x;
    int b = gid / NP, n = gid % NP;
    const float* xb = x + (size_t)b * CCH * NP + n;

    float aq[ICH], ak[ICH], av[ICH];
    #pragma unroll
    for (int i = 0; i < ICH; i++) { aq[i] = 0.f; ak[i] = 0.f; av[i] = 0.f; }

    for (int c = 0; c < CCH; c += 4) {
        float x0 = xb[(size_t)(c + 0) * NP];
        float x1 = xb[(size_t)(c + 1) * NP];
        float x2 = xb[(size_t)(c + 2) * NP];
        float x3 = xb[(size_t)(c + 3) * NP];
        #pragma unroll
        for (int i = 0; i < ICH; i++) {
            float4 wq = *(const float4*)&sWq[i * CCH + c];
            aq[i] = fmaf(wq.x, x0, fmaf(wq.y, x1, fmaf(wq.z, x2, fmaf(wq.w, x3, aq[i]))));
            float4 wk = *(const float4*)&sWk[i * CCH + c];
            ak[i] = fmaf(wk.x, x0, fmaf(wk.y, x1, fmaf(wk.z, x2, fmaf(wk.w, x3, ak[i]))));
            float4 wv = *(const float4*)&sWv[i * CCH + c];
            av[i] = fmaf(wv.x, x0, fmaf(wv.y, x1, fmaf(wv.z, x2, fmaf(wv.w, x3, av[i]))));
        }
    }

    float qf[ICH], kf[ICH];
    #pragma unroll
    for (int i = 0; i < ICH; i++) {
        qf[i] = (aq[i] + sb[i]) * LOG2E;
        kf[i] = ak[i] + sb[ICH + i];
    }
    u32 qhi[8], qlo[8], khi[8], klo[8];
    #pragma unroll
    for (int j = 0; j < 8; j++) {
        __half qh0 = __float2half_rn(qf[2 * j]),     qh1 = __float2half_rn(qf[2 * j + 1]);
        float  qlo0 = qf[2 * j] - __half2float(qh0), qlo1 = qf[2 * j + 1] - __half2float(qh1);
        qhi[j] = pack_f16(qh0, qh1);
        qlo[j] = pack_f16(__float2half_rn(qlo0), __float2half_rn(qlo1));
        __half kh0 = __float2half_rn(kf[2 * j]),     kh1 = __float2half_rn(kf[2 * j + 1]);
        float  klo0 = kf[2 * j] - __half2float(kh0), klo1 = kf[2 * j + 1] - __half2float(kh1);
        khi[j] = pack_f16(kh0, kh1);
        klo[j] = pack_f16(__float2half_rn(klo0), __float2half_rn(klo1));
    }
    u32* qo = g_q2 + (size_t)gid * 16;
    u32* ko = g_k2 + (size_t)gid * 16;
    #pragma unroll
    for (int j = 0; j < 8; j++) { qo[j] = qhi[j]; qo[8 + j] = qlo[j]; }
    // K layout grouped by tg so a thread's 4 fragment words are contiguous (LDS.128)
    #pragma unroll
    for (int tg = 0; tg < 4; tg++) {
        ko[tg * 4 + 0] = khi[tg];
        ko[tg * 4 + 1] = khi[tg + 4];
        ko[tg * 4 + 2] = klo[tg];
        ko[tg * 4 + 3] = klo[tg + 4];
    }
    // V: keys pair-permuted within each 16-group so (b0,b1) is contiguous (LDS.64)
    {
        int idx16 = n & 15;
        int p = idx16 >> 1, e = idx16 & 1;
        int pp = (p < 4) ? (2 * p) : (2 * (p - 4) + 1);
        int nperm = (n & ~15) | (pp * 2 + e);
        unsigned short* vt = g_vt + (size_t)b * 32 * NP + nperm;
        #pragma unroll
        for (int i = 0; i < ICH; i++) {
            float vv = av[i] + sb[2 * ICH + i];
            vt[(size_t)i * NP]        = (unsigned short)(__float_as_uint(vv) >> 16);
            vt[(size_t)(16 + i) * NP] = (unsigned short)(__float_as_uint(lo_of(vv)) >> 16);
        }
    }
}

// ---------------- tile loaders (256 threads) ----------------
static __device__ __forceinline__ void load_k_tile(const char* gk, char* dst, int t, int tid) {
    const char* src = gk + (size_t)t * KT * 64;
    #pragma unroll
    for (int r = 0; r < 2; r++) {
        int idx = r * 256 + tid;
        int key = idx >> 2, c = idx & 3;
        cpasync16(dst + key * 80 + c * 16, src + key * 64 + c * 16);
    }
}
static __device__ __forceinline__ void load_v_tile(const char* gv, char* dst, int t, int tid) {
    #pragma unroll
    for (int r = 0; r < 2; r++) {
        int idx = r * 256 + tid;
        int row = idx >> 4, c = idx & 15;
        cpasync16(dst + row * 288 + c * 16, gv + (size_t)row * (NP * 2) + t * 256 + c * 16);
    }
}

// ============================================================================
// Kernel 2: HMMA flash attention; P single-stream rn-bf16, dn via ones-MMA
// ============================================================================
__global__ void __launch_bounds__(256, 2) attn_kernel(
    const float* __restrict__ x, const float* __restrict__ Wo,
    const float* __restrict__ bo, const float* __restrict__ gamma,
    float* __restrict__ y)
{
    extern __shared__ char smc[];
    const int tid = threadIdx.x;
    const int w = tid >> 5, lane = tid & 31;
    const int wq = w & 3;            // query group (16 queries)
    const int wk = w >> 2;           // key half of each tile
    const int gr = lane >> 2, tg = lane & 3;
    const int b  = blockIdx.x / NQB;
    const int q0 = (blockIdx.x % NQB) * QB;

    float* sWo = (float*)(smc + WO_OFF);
    float* sbo = (float*)(smc + BO_OFF);
    float* sO  = (float*)(smc + SO_OFF);
    for (int i = tid; i < ICH * CCH; i += 256) sWo[i] = Wo[i];
    if (tid < CCH) sbo[tid] = bo[tid];

    // Q fragments for this warp's 16 queries (rows wq*16 + gr, +8)
    const u32* qp  = g_q2 + (size_t)(b * NP + q0 + wq * 16 + gr) * 16;
    const u32* qp8 = qp + 8 * 16;
    u32 qh[4], ql[4];
    qh[0] = qp[tg];     qh[1] = qp8[tg];     qh[2] = qp[tg + 4];  qh[3] = qp8[tg + 4];
    ql[0] = qp[8 + tg]; ql[1] = qp8[8 + tg]; ql[2] = qp[12 + tg]; ql[3] = qp8[12 + tg];

    // ones B-fragment for the denominator MMA (col 0 only)
    const u32 one_b = (gr == 0) ? 0x3F803F80u : 0u;

    // accumulators: oA (Ph*Vh) parity-split, oC (Ph*Vl), oD (Ph*ones) parity-split
    float oA0[2][4] = {}, oA1[2][4] = {}, oC[2][4] = {};
    float oD0[4] = {}, oD1[4] = {};

    const char* gk = (const char*)(g_k2 + (size_t)b * NP * 16);
    const char* gv = (const char*)(g_vt + (size_t)b * 32 * NP);

    load_k_tile(gk, smc + K0_OFF, 0, tid);
    load_v_tile(gv, smc + V0_OFF, 0, tid);
    CP_COMMIT();

    int buf = 0;
    for (int t = 0; t < NT; t++) {
        if (t + 1 < NT) {
            load_k_tile(gk, smc + (buf ? K0_OFF : K1_OFF), t + 1, tid);
            load_v_tile(gv, smc + (buf ? V0_OFF : V1_OFF), t + 1, tid);
            CP_COMMIT();
            asm volatile("cp.async.wait_group 1;" ::: "memory");
        } else {
            asm volatile("cp.async.wait_group 0;" ::: "memory");
        }
        __syncthreads();

        const char* kb = smc + (buf ? K1_OFF : K0_OFF);
        const char* vb = smc + (buf ? V1_OFF : V0_OFF);

        #pragma unroll
        for (int c2 = 0; c2 < 4; c2++) {
            const int ck = wk * 4 + c2;   // this warp's 16-key chunk
            const char* ka = kb + (ck * 16 + gr) * 80 + tg * 16;
            uint4 kw0 = *(const uint4*)ka;              // {hi tg, hi tg+4, lo tg, lo tg+4}
            uint4 kw1 = *(const uint4*)(ka + 8 * 80);
            float sa0[4] = {0.f,0.f,0.f,0.f}, sb0[4] = {0.f,0.f,0.f,0.f};
            float sa1[4] = {0.f,0.f,0.f,0.f}, sb1[4] = {0.f,0.f,0.f,0.f};
            MMA_F16(sa0, qh, kw0.x, kw0.y);
            MMA_F16(sb0, ql, kw0.x, kw0.y);
            MMA_F16(sa0, qh, kw0.z, kw0.w);
            MMA_F16(sa1, qh, kw1.x, kw1.y);
            MMA_F16(sb1, ql, kw1.x, kw1.y);
            MMA_F16(sa1, qh, kw1.z, kw1.w);

            float p00 = ex2f(sa0[0] + sb0[0]), p01 = ex2f(sa0[1] + sb0[1]);
            float p02 = ex2f(sa0[2] + sb0[2]), p03 = ex2f(sa0[3] + sb0[3]);
            float p10 = ex2f(sa1[0] + sb1[0]), p11 = ex2f(sa1[1] + sb1[1]);
            float p12 = ex2f(sa1[2] + sb1[2]), p13 = ex2f(sa1[3] + sb1[3]);
            u32 pah[4];
            pah[0] = pack_bf16_rn(p00, p01); pah[1] = pack_bf16_rn(p02, p03);
            pah[2] = pack_bf16_rn(p10, p11); pah[3] = pack_bf16_rn(p12, p13);

            float (*oAp)[4] = (c2 & 1) ? oA1 : oA0;
            float* oDp = (c2 & 1) ? oD1 : oD0;
            #pragma unroll
            for (int cb = 0; cb < 2; cb++) {
                const char* va = vb + (cb * 8 + gr) * 288 + ck * 32 + tg * 8;
                uint2 vh = *(const uint2*)va;
                uint2 vl = *(const uint2*)(va + 16 * 288);
                MMA_BF16(oAp[cb], pah, vh.x, vh.y);
                MMA_BF16(oC[cb],  pah, vl.x, vl.y);
            }
            MMA_BF16(oDp, pah, one_b, one_b);
        }
        __syncthreads();
        buf ^= 1;
    }

    // combine accumulator streams
    float ro[2][4];
    #pragma unroll
    for (int cb = 0; cb < 2; cb++)
        #pragma unroll
        for (int i = 0; i < 4; i++)
            ro[cb][i] = (oA0[cb][i] + oA1[cb][i]) + oC[cb][i];

    // denominators: valid at tg==0 lanes (col 0) -> broadcast within quad group
    float dnA = __shfl_sync(0xFFFFFFFFu, oD0[0] + oD1[0], gr * 4);
    float dnB = __shfl_sync(0xFFFFFFFFu, oD0[2] + oD1[2], gr * 4);

    // cross-warp-half reduction via smem (aliases dead K0 tile buffer)
    float* part = (float*)(smc + K0_OFF);   // [64][18]: 16 out cols + dn
    const int r0 = wq * 16 + gr, r1 = r0 + 8;
    if (wk == 1) {
        #pragma unroll
        for (int cb = 0; cb < 2; cb++) {
            int col = cb * 8 + tg * 2;
            part[r0 * 18 + col]     = ro[cb][0];
            part[r0 * 18 + col + 1] = ro[cb][1];
            part[r1 * 18 + col]     = ro[cb][2];
            part[r1 * 18 + col + 1] = ro[cb][3];
        }
        if (tg == 0) { part[r0 * 18 + 16] = dnA; part[r1 * 18 + 16] = dnB; }
    }
    __syncthreads();
    if (wk == 0) {
        float id0 = 1.0f / (dnA + part[r0 * 18 + 16]);
        float id1 = 1.0f / (dnB + part[r1 * 18 + 16]);
        #pragma unroll
        for (int cb = 0; cb < 2; cb++) {
            int col = cb * 8 + tg * 2;
            sO[r0 * 17 + col]     = (ro[cb][0] + part[r0 * 18 + col])     * id0;
            sO[r0 * 17 + col + 1] = (ro[cb][1] + part[r0 * 18 + col + 1]) * id0;
            sO[r1 * 17 + col]     = (ro[cb][2] + part[r1 * 18 + col])     * id1;
            sO[r1 * 17 + col + 1] = (ro[cb][3] + part[r1 * 18 + col + 1]) * id1;
        }
    }
    __syncthreads();

    // epilogue: y = gamma * (Wo @ O + bo) + x
    const float gam = gamma[0];
    for (int idx = tid; idx < CCH * QB; idx += 256) {
        int c = idx >> 6, q = idx & 63;
        const float* wr = sWo + c * ICH;
        const float* ov = sO + q * 17;
        float acc = 0.f;
        #pragma unroll
        for (int i = 0; i < ICH; i++) acc = fmaf(wr[i], ov[i], acc);
        size_t gi = ((size_t)(b * CCH + c)) * NP + (q0 + q);
        y[gi] = gam * (acc + sbo[c]) + x[gi];
    }
}

extern "C" void kernel_launch(void* const* d_in, const int* in_sizes, int n_in,
                              void* d_out, int out_size) {
    const float* x     = (const float*)d_in[0];
    const float* Wq    = (const float*)d_in[1];
    const float* bq    = (const float*)d_in[2];
    const float* Wk    = (const float*)d_in[3];
    const float* bk    = (const float*)d_in[4];
    const float* Wv    = (const float*)d_in[5];
    const float* bv    = (const float*)d_in[6];
    const float* Wo    = (const float*)d_in[7];
    const float* bo    = (const float*)d_in[8];
    const float* gamma = (const float*)d_in[9];
    float* y = (float*)d_out;

    cudaFuncSetAttribute(attn_kernel, cudaFuncAttributeMaxDynamicSharedMemorySize, SMEM_BYTES);

    qkv_kernel<<<(BATCH * NP) / 256, 256>>>(x, Wq, bq, Wk, bk, Wv, bv);
    attn_kernel<<<BATCH * NQB, 256, SMEM_BYTES>>>(x, Wo, bo, gamma, y);
}

// round 12
// speedup vs baseline: 1.2528x; 1.0903x over previous
#include <cuda_runtime.h>
#include <cuda_fp16.h>
#include <cstdint>

#define BATCH 2
#define CCH 128
#define ICH 16
#define NP 9216
#define QB 64                // queries per CTA
#define KT 128               // keys per tile
#define NT (NP / KT)         // 72
#define NQB (NP / QB)        // 144
#define LOG2E 1.4426950408889634f

// smem byte offsets: K stride 64B/key (contiguous, conflict-free LDS.128),
// V stride 288B/row (conflict-free LDS.64)
#define K0_OFF 0
#define K1_OFF 8192
#define V0_OFF 16384
#define V1_OFF 25600
#define WO_OFF 34816
#define BO_OFF 43008
#define SO_OFF 43520
#define SMEM_BYTES 47872
// cross-warp partial area aliases K0/K1 after the mainloop: 3 slots x [64][18]

typedef unsigned int u32;

__device__ __align__(16) u32 g_q2[BATCH * NP * 16];            // per query: 8 fp16-hi pair words, 8 lo
__device__ __align__(16) u32 g_k2[BATCH * NP * 16];            // per key: tg-grouped {hi[tg],hi[tg+4],lo[tg],lo[tg+4]}
__device__ __align__(16) unsigned short g_vt[BATCH * 32 * NP]; // rows 0-15 Vh (bf16), 16-31 Vl; keys pair-permuted per 16

static __device__ __forceinline__ float ex2f(float x) {
    float r; asm("ex2.approx.f32 %0, %1;" : "=f"(r) : "f"(x)); return r;
}
static __device__ __forceinline__ u32 pack_bf16_rn(float p0, float p1) {
    u32 d; asm("cvt.rn.satfinite.bf16x2.f32 %0, %1, %2;" : "=r"(d) : "f"(p1), "f"(p0)); return d;
}
static __device__ __forceinline__ float lo_of(float a) {
    return a - __uint_as_float(__float_as_uint(a) & 0xFFFF0000u);
}
static __device__ __forceinline__ u32 pack_f16(__half a, __half b) {
    return (u32)__half_as_ushort(a) | ((u32)__half_as_ushort(b) << 16);
}
static __device__ __forceinline__ void cpasync16(void* s, const void* g) {
    u32 a = (u32)__cvta_generic_to_shared(s);
    asm volatile("cp.async.cg.shared.global [%0], [%1], 16;" :: "r"(a), "l"(g));
}
#define CP_COMMIT() asm volatile("cp.async.commit_group;" ::: "memory")

#define MMA_F16(d, a, b0, b1) \
    asm volatile("mma.sync.aligned.m16n8k16.row.col.f32.f16.f16.f32 " \
        "{%0,%1,%2,%3},{%4,%5,%6,%7},{%8,%9},{%0,%1,%2,%3};" \
        : "+f"((d)[0]), "+f"((d)[1]), "+f"((d)[2]), "+f"((d)[3]) \
        : "r"((a)[0]), "r"((a)[1]), "r"((a)[2]), "r"((a)[3]), "r"(b0), "r"(b1))

#define MMA_BF16(d, a, b0, b1) \
    asm volatile("mma.sync.aligned.m16n8k16.row.col.f32.bf16.bf16.f32 " \
        "{%0,%1,%2,%3},{%4,%5,%6,%7},{%8,%9},{%0,%1,%2,%3};" \
        : "+f"((d)[0]), "+f"((d)[1]), "+f"((d)[2]), "+f"((d)[3]) \
        : "r"((a)[0]), "r"((a)[1]), "r"((a)[2]), "r"((a)[3]), "r"(b0), "r"(b1))

// ============================================================================
// Kernel 1: qkv projections -> fp16 hi/lo Q,K ; bf16 hi/lo V (transposed)
// ============================================================================
__global__ void __launch_bounds__(256) qkv_kernel(
    const float* __restrict__ x,
    const float* __restrict__ Wq, const float* __restrict__ bq,
    const float* __restrict__ Wk, const float* __restrict__ bk,
    const float* __restrict__ Wv, const float* __restrict__ bv)
{
    __shared__ float sWq[ICH * CCH], sWk[ICH * CCH], sWv[ICH * CCH];
    __shared__ float sb[3 * ICH];
    for (int i = threadIdx.x; i < ICH * CCH; i += 256) {
        sWq[i] = Wq[i]; sWk[i] = Wk[i]; sWv[i] = Wv[i];
    }
    if (threadIdx.x < ICH)            sb[threadIdx.x] = bq[threadIdx.x];
    else if (threadIdx.x < 2 * ICH)   sb[threadIdx.x] = bk[threadIdx.x - ICH];
    else if (threadIdx.x < 3 * ICH)   sb[threadIdx.x] = bv[threadIdx.x - 2 * ICH];
    __syncthreads();

    int gid = blockIdx.x * 256 + threadIdx.x;
    int b = gid / NP, n = gid % NP;
    const float* xb = x + (size_t)b * CCH * NP + n;

    float aq[ICH], ak[ICH], av[ICH];
    #pragma unroll
    for (int i = 0; i < ICH; i++) { aq[i] = 0.f; ak[i] = 0.f; av[i] = 0.f; }

    for (int c = 0; c < CCH; c += 4) {
        float x0 = xb[(size_t)(c + 0) * NP];
        float x1 = xb[(size_t)(c + 1) * NP];
        float x2 = xb[(size_t)(c + 2) * NP];
        float x3 = xb[(size_t)(c + 3) * NP];
        #pragma unroll
        for (int i = 0; i < ICH; i++) {
            float4 wq = *(const float4*)&sWq[i * CCH + c];
            aq[i] = fmaf(wq.x, x0, fmaf(wq.y, x1, fmaf(wq.z, x2, fmaf(wq.w, x3, aq[i]))));
            float4 wk = *(const float4*)&sWk[i * CCH + c];
            ak[i] = fmaf(wk.x, x0, fmaf(wk.y, x1, fmaf(wk.z, x2, fmaf(wk.w, x3, ak[i]))));
            float4 wv = *(const float4*)&sWv[i * CCH + c];
            av[i] = fmaf(wv.x, x0, fmaf(wv.y, x1, fmaf(wv.z, x2, fmaf(wv.w, x3, av[i]))));
        }
    }

    float qf[ICH], kf[ICH];
    #pragma unroll
    for (int i = 0; i < ICH; i++) {
        qf[i] = (aq[i] + sb[i]) * LOG2E;
        kf[i] = ak[i] + sb[ICH + i];
    }
    u32 qhi[8], qlo[8], khi[8], klo[8];
    #pragma unroll
    for (int j = 0; j < 8; j++) {
        __half qh0 = __float2half_rn(qf[2 * j]),     qh1 = __float2half_rn(qf[2 * j + 1]);
        float  qlo0 = qf[2 * j] - __half2float(qh0), qlo1 = qf[2 * j + 1] - __half2float(qh1);
        qhi[j] = pack_f16(qh0, qh1);
        qlo[j] = pack_f16(__float2half_rn(qlo0), __float2half_rn(qlo1));
        __half kh0 = __float2half_rn(kf[2 * j]),     kh1 = __float2half_rn(kf[2 * j + 1]);
        float  klo0 = kf[2 * j] - __half2float(kh0), klo1 = kf[2 * j + 1] - __half2float(kh1);
        khi[j] = pack_f16(kh0, kh1);
        klo[j] = pack_f16(__float2half_rn(klo0), __float2half_rn(klo1));
    }
    u32* qo = g_q2 + (size_t)gid * 16;
    u32* ko = g_k2 + (size_t)gid * 16;
    #pragma unroll
    for (int j = 0; j < 8; j++) { qo[j] = qhi[j]; qo[8 + j] = qlo[j]; }
    // K layout grouped by tg so a thread's 4 fragment words are contiguous (LDS.128)
    #pragma unroll
    for (int tg = 0; tg < 4; tg++) {
        ko[tg * 4 + 0] = khi[tg];
        ko[tg * 4 + 1] = khi[tg + 4];
        ko[tg * 4 + 2] = klo[tg];
        ko[tg * 4 + 3] = klo[tg + 4];
    }
    // V: keys pair-permuted within each 16-group so (b0,b1) is contiguous (LDS.64)
    {
        int idx16 = n & 15;
        int p = idx16 >> 1, e = idx16 & 1;
        int pp = (p < 4) ? (2 * p) : (2 * (p - 4) + 1);
        int nperm = (n & ~15) | (pp * 2 + e);
        unsigned short* vt = g_vt + (size_t)b * 32 * NP + nperm;
        #pragma unroll
        for (int i = 0; i < ICH; i++) {
            float vv = av[i] + sb[2 * ICH + i];
            vt[(size_t)i * NP]        = (unsigned short)(__float_as_uint(vv) >> 16);
            vt[(size_t)(16 + i) * NP] = (unsigned short)(__float_as_uint(lo_of(vv)) >> 16);
        }
    }
}

// ---------------- tile loaders (256 threads) ----------------
static __device__ __forceinline__ void load_k_tile(const char* gk, char* dst, int t, int tid) {
    const char* src = gk + (size_t)t * KT * 64;   // contiguous 8 KB
    #pragma unroll
    for (int r = 0; r < 2; r++) {
        int idx = r * 256 + tid;
        cpasync16(dst + idx * 16, src + idx * 16);
    }
}
static __device__ __forceinline__ void load_v_tile(const char* gv, char* dst, int t, int tid) {
    #pragma unroll
    for (int r = 0; r < 2; r++) {
        int idx = r * 256 + tid;
        int row = idx >> 4, c = idx & 15;
        cpasync16(dst + row * 288 + c * 16, gv + (size_t)row * (NP * 2) + t * 256 + c * 16);
    }
}

// ============================================================================
// Kernel 2: HMMA flash attention; 32q x 32k per warp (B-frags amortized 2x)
// ============================================================================
__global__ void __launch_bounds__(256, 2) attn_kernel(
    const float* __restrict__ x, const float* __restrict__ Wo,
    const float* __restrict__ bo, const float* __restrict__ gamma,
    float* __restrict__ y)
{
    extern __shared__ char smc[];
    const int tid = threadIdx.x;
    const int w = tid >> 5, lane = tid & 31;
    const int wq = w & 1;            // query half (32 queries)
    const int wk = w >> 1;           // key quarter of each tile
    const int gr = lane >> 2, tg = lane & 3;
    const int b  = blockIdx.x / NQB;
    const int q0 = (blockIdx.x % NQB) * QB;

    float* sWo = (float*)(smc + WO_OFF);
    float* sbo = (float*)(smc + BO_OFF);
    float* sO  = (float*)(smc + SO_OFF);
    for (int i = tid; i < ICH * CCH; i += 256) sWo[i] = Wo[i];
    if (tid < CCH) sbo[tid] = bo[tid];

    // Q fragments: two A-sets (s=0: rows wq*32+0..15, s=1: rows +16..31)
    u32 qh[2][4], ql[2][4];
    #pragma unroll
    for (int s = 0; s < 2; s++) {
        const u32* qp  = g_q2 + (size_t)(b * NP + q0 + wq * 32 + s * 16 + gr) * 16;
        const u32* qp8 = qp + 8 * 16;
        qh[s][0] = qp[tg];     qh[s][1] = qp8[tg];     qh[s][2] = qp[tg + 4];  qh[s][3] = qp8[tg + 4];
        ql[s][0] = qp[8 + tg]; ql[s][1] = qp8[8 + tg]; ql[s][2] = qp[12 + tg]; ql[s][3] = qp8[12 + tg];
    }

    const u32 one_b = (gr == 0) ? 0x3F803F80u : 0u;

    float oA[2][2][4] = {}, oC[2][2][4] = {};   // [set][cb][4]
    float oD[2][4] = {};                         // [set][4] ones-column

    const char* gk = (const char*)(g_k2 + (size_t)b * NP * 16);
    const char* gv = (const char*)(g_vt + (size_t)b * 32 * NP);

    load_k_tile(gk, smc + K0_OFF, 0, tid);
    load_v_tile(gv, smc + V0_OFF, 0, tid);
    CP_COMMIT();

    int buf = 0;
    for (int t = 0; t < NT; t++) {
        if (t + 1 < NT) {
            load_k_tile(gk, smc + (buf ? K0_OFF : K1_OFF), t + 1, tid);
            load_v_tile(gv, smc + (buf ? V0_OFF : V1_OFF), t + 1, tid);
            CP_COMMIT();
            asm volatile("cp.async.wait_group 1;" ::: "memory");
        } else {
            asm volatile("cp.async.wait_group 0;" ::: "memory");
        }
        __syncthreads();

        const char* kb = smc + (buf ? K1_OFF : K0_OFF);
        const char* vb = smc + (buf ? V1_OFF : V0_OFF);

        #pragma unroll
        for (int c2 = 0; c2 < 2; c2++) {
            const int ck = wk * 2 + c2;   // 16-key chunk
            const char* ka = kb + (ck * 16 + gr) * 64 + tg * 16;
            uint4 kw0 = *(const uint4*)ka;              // {hi tg, hi tg+4, lo tg, lo tg+4}
            uint4 kw1 = *(const uint4*)(ka + 8 * 64);
            // V fragments, shared across both A-sets
            uint2 vh[2], vl[2];
            #pragma unroll
            for (int cb = 0; cb < 2; cb++) {
                const char* va = vb + (cb * 8 + gr) * 288 + ck * 32 + tg * 8;
                vh[cb] = *(const uint2*)va;
                vl[cb] = *(const uint2*)(va + 16 * 288);
            }
            #pragma unroll
            for (int s = 0; s < 2; s++) {
                float sa0[4] = {0.f,0.f,0.f,0.f}, sb0[4] = {0.f,0.f,0.f,0.f};
                float sa1[4] = {0.f,0.f,0.f,0.f}, sb1[4] = {0.f,0.f,0.f,0.f};
                MMA_F16(sa0, qh[s], kw0.x, kw0.y);
                MMA_F16(sb0, ql[s], kw0.x, kw0.y);
                MMA_F16(sa0, qh[s], kw0.z, kw0.w);
                MMA_F16(sa1, qh[s], kw1.x, kw1.y);
                MMA_F16(sb1, ql[s], kw1.x, kw1.y);
                MMA_F16(sa1, qh[s], kw1.z, kw1.w);

                float p00 = ex2f(sa0[0] + sb0[0]), p01 = ex2f(sa0[1] + sb0[1]);
                float p02 = ex2f(sa0[2] + sb0[2]), p03 = ex2f(sa0[3] + sb0[3]);
                float p10 = ex2f(sa1[0] + sb1[0]), p11 = ex2f(sa1[1] + sb1[1]);
                float p12 = ex2f(sa1[2] + sb1[2]), p13 = ex2f(sa1[3] + sb1[3]);
                u32 pah[4];
                pah[0] = pack_bf16_rn(p00, p01); pah[1] = pack_bf16_rn(p02, p03);
                pah[2] = pack_bf16_rn(p10, p11); pah[3] = pack_bf16_rn(p12, p13);

                #pragma unroll
                for (int cb = 0; cb < 2; cb++) {
                    MMA_BF16(oA[s][cb], pah, vh[cb].x, vh[cb].y);
                    MMA_BF16(oC[s][cb], pah, vl[cb].x, vl[cb].y);
                }
                MMA_BF16(oD[s], pah, one_b, one_b);
            }
        }
        __syncthreads();
        buf ^= 1;
    }

    // combine value streams
    float ro[2][2][4];
    #pragma unroll
    for (int s = 0; s < 2; s++)
        #pragma unroll
        for (int cb = 0; cb < 2; cb++)
            #pragma unroll
            for (int i = 0; i < 4; i++)
                ro[s][cb][i] = oA[s][cb][i] + oC[s][cb][i];

    // cross-warp reduction: wk 1..3 write partials into dead K0/K1 region
    float* part = (float*)smc;   // 3 slots x [64][18]
    if (wk > 0) {
        float* ps = part + (wk - 1) * 64 * 18;
        #pragma unroll
        for (int s = 0; s < 2; s++) {
            int qi0 = wq * 32 + s * 16 + gr, qi1 = qi0 + 8;
            #pragma unroll
            for (int cb = 0; cb < 2; cb++) {
                int col = cb * 8 + tg * 2;
                ps[qi0 * 18 + col]     = ro[s][cb][0];
                ps[qi0 * 18 + col + 1] = ro[s][cb][1];
                ps[qi1 * 18 + col]     = ro[s][cb][2];
                ps[qi1 * 18 + col + 1] = ro[s][cb][3];
            }
            if (tg == 0) {
                ps[qi0 * 18 + 16] = oD[s][0];
                ps[qi1 * 18 + 16] = oD[s][2];
            }
        }
    }
    __syncthreads();
    if (wk == 0) {
        #pragma unroll
        for (int s = 0; s < 2; s++) {
            int qi0 = wq * 32 + s * 16 + gr, qi1 = qi0 + 8;
            float dnA = __shfl_sync(0xFFFFFFFFu, oD[s][0], lane & ~3);
            float dnB = __shfl_sync(0xFFFFFFFFu, oD[s][2], lane & ~3);
            #pragma unroll
            for (int k = 0; k < 3; k++) {
                dnA += part[k * 64 * 18 + qi0 * 18 + 16];
                dnB += part[k * 64 * 18 + qi1 * 18 + 16];
            }
            float id0 = 1.0f / dnA, id1 = 1.0f / dnB;
            #pragma unroll
            for (int cb = 0; cb < 2; cb++) {
                int col = cb * 8 + tg * 2;
                float a0 = ro[s][cb][0], a1 = ro[s][cb][1];
                float a2 = ro[s][cb][2], a3 = ro[s][cb][3];
                #pragma unroll
                for (int k = 0; k < 3; k++) {
                    const float* ps = part + k * 64 * 18;
                    a0 += ps[qi0 * 18 + col];     a1 += ps[qi0 * 18 + col + 1];
                    a2 += ps[qi1 * 18 + col];     a3 += ps[qi1 * 18 + col + 1];
                }
                sO[qi0 * 17 + col]     = a0 * id0;
                sO[qi0 * 17 + col + 1] = a1 * id0;
                sO[qi1 * 17 + col]     = a2 * id1;
                sO[qi1 * 17 + col + 1] = a3 * id1;
            }
        }
    }
    __syncthreads();

    // epilogue: y = gamma * (Wo @ O + bo) + x
    const float gam = gamma[0];
    for (int idx = tid; idx < CCH * QB; idx += 256) {
        int c = idx >> 6, q = idx & 63;
        const float* wr = sWo + c * ICH;
        const float* ov = sO + q * 17;
        float acc = 0.f;
        #pragma unroll
        for (int i = 0; i < ICH; i++) acc = fmaf(wr[i], ov[i], acc);
        size_t gi = ((size_t)(b * CCH + c)) * NP + (q0 + q);
        y[gi] = gam * (acc + sbo[c]) + x[gi];
    }
}

extern "C" void kernel_launch(void* const* d_in, const int* in_sizes, int n_in,
                              void* d_out, int out_size) {
    const float* x     = (const float*)d_in[0];
    const float* Wq    = (const float*)d_in[1];
    const float* bq    = (const float*)d_in[2];
    const float* Wk    = (const float*)d_in[3];
    const float* bk    = (const float*)d_in[4];
    const float* Wv    = (const float*)d_in[5];
    const float* bv    = (const float*)d_in[6];
    const float* Wo    = (const float*)d_in[7];
    const float* bo    = (const float*)d_in[8];
    const float* gamma = (const float*)d_in[9];
    float* y = (float*)d_out;

    cudaFuncSetAttribute(attn_kernel, cudaFuncAttributeMaxDynamicSharedMemorySize, SMEM_BYTES);

    qkv_kernel<<<(BATCH * NP) / 256, 256>>>(x, Wq, bq, Wk, bk, Wv, bv);
    attn_kernel<<<BATCH * NQB, 256, SMEM_BYTES>>>(x, Wo, bo, gamma, y);
}

// round 13
// speedup vs baseline: 1.3541x; 1.0808x over previous
#include <cuda_runtime.h>
#include <cuda_fp16.h>
#include <cstdint>

#define BATCH 2
#define CCH 128
#define ICH 16
#define NP 9216
#define QB 64                // queries per CTA
#define KT 256               // keys per tile
#define NT (NP / KT)         // 36
#define NQB (NP / QB)        // 144
#define LOG2E 1.4426950408889634f

// smem: 3 buffers of (K: 256 keys x 32B = 8192) + (V: 32 rows x 544B = 17408)
#define BUF_STRIDE 25600
#define KOFF 0
#define VOFF 8192
#define WO_OFF 76800
#define BO_OFF 84992
#define SO_OFF 85504
#define SMEM_BYTES 89856
// cross-warp partials alias buffer region after mainloop: 3 slots x [64][18]

typedef unsigned int u32;

__device__ __align__(16) u32 g_q2[BATCH * NP * 16];            // per query: 8 fp16-hi pair words, 8 lo
__device__ __align__(16) u32 g_k2[BATCH * NP * 8];             // per key (fp16 single): [tg*2]={k[tg]}, [tg*2+1]={k[tg+4]}
__device__ __align__(16) unsigned short g_vt[BATCH * 32 * NP]; // rows 0-15 Vh (bf16), 16-31 Vl; keys pair-permuted per 16

static __device__ __forceinline__ float ex2f(float x) {
    float r; asm("ex2.approx.f32 %0, %1;" : "=f"(r) : "f"(x)); return r;
}
static __device__ __forceinline__ u32 pack_bf16_rn(float p0, float p1) {
    u32 d; asm("cvt.rn.satfinite.bf16x2.f32 %0, %1, %2;" : "=r"(d) : "f"(p1), "f"(p0)); return d;
}
static __device__ __forceinline__ float lo_of(float a) {
    return a - __uint_as_float(__float_as_uint(a) & 0xFFFF0000u);
}
static __device__ __forceinline__ u32 pack_f16(__half a, __half b) {
    return (u32)__half_as_ushort(a) | ((u32)__half_as_ushort(b) << 16);
}
static __device__ __forceinline__ void cpasync16(void* s, const void* g) {
    u32 a = (u32)__cvta_generic_to_shared(s);
    asm volatile("cp.async.cg.shared.global [%0], [%1], 16;" :: "r"(a), "l"(g));
}
#define CP_COMMIT() asm volatile("cp.async.commit_group;" ::: "memory")

#define MMA_F16(d, a, b0, b1) \
    asm volatile("mma.sync.aligned.m16n8k16.row.col.f32.f16.f16.f32 " \
        "{%0,%1,%2,%3},{%4,%5,%6,%7},{%8,%9},{%0,%1,%2,%3};" \
        : "+f"((d)[0]), "+f"((d)[1]), "+f"((d)[2]), "+f"((d)[3]) \
        : "r"((a)[0]), "r"((a)[1]), "r"((a)[2]), "r"((a)[3]), "r"(b0), "r"(b1))

#define MMA_BF16(d, a, b0, b1) \
    asm volatile("mma.sync.aligned.m16n8k16.row.col.f32.bf16.bf16.f32 " \
        "{%0,%1,%2,%3},{%4,%5,%6,%7},{%8,%9},{%0,%1,%2,%3};" \
        : "+f"((d)[0]), "+f"((d)[1]), "+f"((d)[2]), "+f"((d)[3]) \
        : "r"((a)[0]), "r"((a)[1]), "r"((a)[2]), "r"((a)[3]), "r"(b0), "r"(b1))

// ============================================================================
// Kernel 1: qkv projections -> fp16 hi/lo Q ; fp16 single K ; bf16 hi/lo V
// ============================================================================
__global__ void __launch_bounds__(256) qkv_kernel(
    const float* __restrict__ x,
    const float* __restrict__ Wq, const float* __restrict__ bq,
    const float* __restrict__ Wk, const float* __restrict__ bk,
    const float* __restrict__ Wv, const float* __restrict__ bv)
{
    __shared__ float sWq[ICH * CCH], sWk[ICH * CCH], sWv[ICH * CCH];
    __shared__ float sb[3 * ICH];
    for (int i = threadIdx.x; i < ICH * CCH; i += 256) {
        sWq[i] = Wq[i]; sWk[i] = Wk[i]; sWv[i] = Wv[i];
    }
    if (threadIdx.x < ICH)            sb[threadIdx.x] = bq[threadIdx.x];
    else if (threadIdx.x < 2 * ICH)   sb[threadIdx.x] = bk[threadIdx.x - ICH];
    else if (threadIdx.x < 3 * ICH)   sb[threadIdx.x] = bv[threadIdx.x - 2 * ICH];
    __syncthreads();

    int gid = blockIdx.x * 256 + threadIdx.x;
    int b = gid / NP, n = gid % NP;
    const float* xb = x + (size_t)b * CCH * NP + n;

    float aq[ICH], ak[ICH], av[ICH];
    #pragma unroll
    for (int i = 0; i < ICH; i++) { aq[i] = 0.f; ak[i] = 0.f; av[i] = 0.f; }

    for (int c = 0; c < CCH; c += 4) {
        float x0 = xb[(size_t)(c + 0) * NP];
        float x1 = xb[(size_t)(c + 1) * NP];
        float x2 = xb[(size_t)(c + 2) * NP];
        float x3 = xb[(size_t)(c + 3) * NP];
        #pragma unroll
        for (int i = 0; i < ICH; i++) {
            float4 wq = *(const float4*)&sWq[i * CCH + c];
            aq[i] = fmaf(wq.x, x0, fmaf(wq.y, x1, fmaf(wq.z, x2, fmaf(wq.w, x3, aq[i]))));
            float4 wk = *(const float4*)&sWk[i * CCH + c];
            ak[i] = fmaf(wk.x, x0, fmaf(wk.y, x1, fmaf(wk.z, x2, fmaf(wk.w, x3, ak[i]))));
            float4 wv = *(const float4*)&sWv[i * CCH + c];
            av[i] = fmaf(wv.x, x0, fmaf(wv.y, x1, fmaf(wv.z, x2, fmaf(wv.w, x3, av[i]))));
        }
    }

    float qf[ICH], kf[ICH];
    #pragma unroll
    for (int i = 0; i < ICH; i++) {
        qf[i] = (aq[i] + sb[i]) * LOG2E;
        kf[i] = ak[i] + sb[ICH + i];
    }
    u32 qhi[8], qlo[8], khi[8];
    #pragma unroll
    for (int j = 0; j < 8; j++) {
        __half qh0 = __float2half_rn(qf[2 * j]),     qh1 = __float2half_rn(qf[2 * j + 1]);
        float  qlo0 = qf[2 * j] - __half2float(qh0), qlo1 = qf[2 * j + 1] - __half2float(qh1);
        qhi[j] = pack_f16(qh0, qh1);
        qlo[j] = pack_f16(__float2half_rn(qlo0), __float2half_rn(qlo1));
        khi[j] = pack_f16(__float2half_rn(kf[2 * j]), __float2half_rn(kf[2 * j + 1]));
    }
    u32* qo = g_q2 + (size_t)gid * 16;
    u32* ko = g_k2 + (size_t)gid * 8;
    #pragma unroll
    for (int j = 0; j < 8; j++) { qo[j] = qhi[j]; qo[8 + j] = qlo[j]; }
    // K single fp16, tg-interleaved so a thread's 2 fragment words are one LDS.64
    #pragma unroll
    for (int tg = 0; tg < 4; tg++) {
        ko[tg * 2 + 0] = khi[tg];
        ko[tg * 2 + 1] = khi[tg + 4];
    }
    // V: keys pair-permuted within each 16-group so (b0,b1) is contiguous (LDS.64)
    {
        int idx16 = n & 15;
        int p = idx16 >> 1, e = idx16 & 1;
        int pp = (p < 4) ? (2 * p) : (2 * (p - 4) + 1);
        int nperm = (n & ~15) | (pp * 2 + e);
        unsigned short* vt = g_vt + (size_t)b * 32 * NP + nperm;
        #pragma unroll
        for (int i = 0; i < ICH; i++) {
            float vv = av[i] + sb[2 * ICH + i];
            vt[(size_t)i * NP]        = (unsigned short)(__float_as_uint(vv) >> 16);
            vt[(size_t)(16 + i) * NP] = (unsigned short)(__float_as_uint(lo_of(vv)) >> 16);
        }
    }
}

// ---------------- tile loaders (256 threads, KT=256) ----------------
static __device__ __forceinline__ void load_tile(const char* gk, const char* gv,
                                                 char* dst, int t, int tid) {
    const char* ksrc = gk + (size_t)t * KT * 32;   // contiguous 8 KB
    #pragma unroll
    for (int r = 0; r < 2; r++) {
        int idx = r * 256 + tid;
        cpasync16(dst + KOFF + idx * 16, ksrc + idx * 16);
    }
    #pragma unroll
    for (int r = 0; r < 4; r++) {
        int idx = r * 256 + tid;
        int row = idx >> 5, c = idx & 31;
        cpasync16(dst + VOFF + row * 544 + c * 16,
                  gv + (size_t)row * (NP * 2) + t * 512 + c * 16);
    }
    CP_COMMIT();
}

// ============================================================================
// Kernel 2: HMMA flash attention; K-single fp16, 3-buffer 1-sync pipeline
// ============================================================================
__global__ void __launch_bounds__(256, 2) attn_kernel(
    const float* __restrict__ x, const float* __restrict__ Wo,
    const float* __restrict__ bo, const float* __restrict__ gamma,
    float* __restrict__ y)
{
    extern __shared__ char smc[];
    const int tid = threadIdx.x;
    const int w = tid >> 5, lane = tid & 31;
    const int wq = w & 1;            // query half (32 queries)
    const int wk = w >> 1;           // key quarter of each tile (64 keys)
    const int gr = lane >> 2, tg = lane & 3;
    const int b  = blockIdx.x / NQB;
    const int q0 = (blockIdx.x % NQB) * QB;

    float* sWo = (float*)(smc + WO_OFF);
    float* sbo = (float*)(smc + BO_OFF);
    float* sO  = (float*)(smc + SO_OFF);
    for (int i = tid; i < ICH * CCH; i += 256) sWo[i] = Wo[i];
    if (tid < CCH) sbo[tid] = bo[tid];

    // Q fragments: two A-sets (s=0: rows wq*32+0..15, s=1: rows +16..31)
    u32 qh[2][4], ql[2][4];
    #pragma unroll
    for (int s = 0; s < 2; s++) {
        const u32* qp  = g_q2 + (size_t)(b * NP + q0 + wq * 32 + s * 16 + gr) * 16;
        const u32* qp8 = qp + 8 * 16;
        qh[s][0] = qp[tg];     qh[s][1] = qp8[tg];     qh[s][2] = qp[tg + 4];  qh[s][3] = qp8[tg + 4];
        ql[s][0] = qp[8 + tg]; ql[s][1] = qp8[8 + tg]; ql[s][2] = qp[12 + tg]; ql[s][3] = qp8[12 + tg];
    }

    const u32 one_b = (gr == 0) ? 0x3F803F80u : 0u;   // bf16 ones, col 0

    float oA[2][2][4] = {}, oC[2][2][4] = {};   // [set][cb][4]
    float oD[2][4] = {};                         // [set][4] ones-column

    const char* gk = (const char*)(g_k2 + (size_t)b * NP * 8);
    const char* gv = (const char*)(g_vt + (size_t)b * 32 * NP);

    load_tile(gk, gv, smc + 0 * BUF_STRIDE, 0, tid);
    load_tile(gk, gv, smc + 1 * BUF_STRIDE, 1, tid);

    int bidx = 0;   // t % 3
    for (int t = 0; t < NT; t++) {
        if (t + 1 < NT) { asm volatile("cp.async.wait_group 1;" ::: "memory"); }
        else            { asm volatile("cp.async.wait_group 0;" ::: "memory"); }
        __syncthreads();
        if (t + 2 < NT) {
            int nb = bidx + 2; if (nb >= 3) nb -= 3;
            load_tile(gk, gv, smc + nb * BUF_STRIDE, t + 2, tid);
        }

        const char* kb = smc + bidx * BUF_STRIDE + KOFF;
        const char* vb = smc + bidx * BUF_STRIDE + VOFF;

        #pragma unroll
        for (int c2 = 0; c2 < 4; c2++) {
            const int ck = wk * 4 + c2;   // 16-key chunk (of 16 per tile)
            const char* ka = kb + (ck * 16 + gr) * 32 + tg * 8;
            uint2 kw0 = *(const uint2*)ka;
            uint2 kw1 = *(const uint2*)(ka + 8 * 32);
            uint2 vh[2], vl[2];
            #pragma unroll
            for (int cb = 0; cb < 2; cb++) {
                const char* va = vb + (cb * 8 + gr) * 544 + ck * 32 + tg * 8;
                vh[cb] = *(const uint2*)va;
                vl[cb] = *(const uint2*)(va + 16 * 544);
            }
            #pragma unroll
            for (int s = 0; s < 2; s++) {
                float sa0[4] = {0.f,0.f,0.f,0.f}, sb0[4] = {0.f,0.f,0.f,0.f};
                float sa1[4] = {0.f,0.f,0.f,0.f}, sb1[4] = {0.f,0.f,0.f,0.f};
                MMA_F16(sa0, qh[s], kw0.x, kw0.y);
                MMA_F16(sb0, ql[s], kw0.x, kw0.y);
                MMA_F16(sa1, qh[s], kw1.x, kw1.y);
                MMA_F16(sb1, ql[s], kw1.x, kw1.y);

                float p00 = ex2f(sa0[0] + sb0[0]), p01 = ex2f(sa0[1] + sb0[1]);
                float p02 = ex2f(sa0[2] + sb0[2]), p03 = ex2f(sa0[3] + sb0[3]);
                float p10 = ex2f(sa1[0] + sb1[0]), p11 = ex2f(sa1[1] + sb1[1]);
                float p12 = ex2f(sa1[2] + sb1[2]), p13 = ex2f(sa1[3] + sb1[3]);
                u32 pah[4];
                pah[0] = pack_bf16_rn(p00, p01); pah[1] = pack_bf16_rn(p02, p03);
                pah[2] = pack_bf16_rn(p10, p11); pah[3] = pack_bf16_rn(p12, p13);

                #pragma unroll
                for (int cb = 0; cb < 2; cb++) {
                    MMA_BF16(oA[s][cb], pah, vh[cb].x, vh[cb].y);
                    MMA_BF16(oC[s][cb], pah, vl[cb].x, vl[cb].y);
                }
                MMA_BF16(oD[s], pah, one_b, one_b);
            }
        }
        if (++bidx == 3) bidx = 0;
    }

    float ro[2][2][4];
    #pragma unroll
    for (int s = 0; s < 2; s++)
        #pragma unroll
        for (int cb = 0; cb < 2; cb++)
            #pragma unroll
            for (int i = 0; i < 4; i++)
                ro[s][cb][i] = oA[s][cb][i] + oC[s][cb][i];

    __syncthreads();   // everyone done with tile buffers; alias partials
    float* part = (float*)smc;   // 3 slots x [64][18]
    if (wk > 0) {
        float* ps = part + (wk - 1) * 64 * 18;
        #pragma unroll
        for (int s = 0; s < 2; s++) {
            int qi0 = wq * 32 + s * 16 + gr, qi1 = qi0 + 8;
            #pragma unroll
            for (int cb = 0; cb < 2; cb++) {
                int col = cb * 8 + tg * 2;
                ps[qi0 * 18 + col]     = ro[s][cb][0];
                ps[qi0 * 18 + col + 1] = ro[s][cb][1];
                ps[qi1 * 18 + col]     = ro[s][cb][2];
                ps[qi1 * 18 + col + 1] = ro[s][cb][3];
            }
            if (tg == 0) {
                ps[qi0 * 18 + 16] = oD[s][0];
                ps[qi1 * 18 + 16] = oD[s][2];
            }
        }
    }
    __syncthreads();
    if (wk == 0) {
        #pragma unroll
        for (int s = 0; s < 2; s++) {
            int qi0 = wq * 32 + s * 16 + gr, qi1 = qi0 + 8;
            float dnA = __shfl_sync(0xFFFFFFFFu, oD[s][0], lane & ~3);
            float dnB = __shfl_sync(0xFFFFFFFFu, oD[s][2], lane & ~3);
            #pragma unroll
            for (int k = 0; k < 3; k++) {
                dnA += part[k * 64 * 18 + qi0 * 18 + 16];
                dnB += part[k * 64 * 18 + qi1 * 18 + 16];
            }
            float id0 = 1.0f / dnA, id1 = 1.0f / dnB;
            #pragma unroll
            for (int cb = 0; cb < 2; cb++) {
                int col = cb * 8 + tg * 2;
                float a0 = ro[s][cb][0], a1 = ro[s][cb][1];
                float a2 = ro[s][cb][2], a3 = ro[s][cb][3];
                #pragma unroll
                for (int k = 0; k < 3; k++) {
                    const float* ps = part + k * 64 * 18;
                    a0 += ps[qi0 * 18 + col];     a1 += ps[qi0 * 18 + col + 1];
                    a2 += ps[qi1 * 18 + col];     a3 += ps[qi1 * 18 + col + 1];
                }
                sO[qi0 * 17 + col]     = a0 * id0;
                sO[qi0 * 17 + col + 1] = a1 * id0;
                sO[qi1 * 17 + col]     = a2 * id1;
                sO[qi1 * 17 + col + 1] = a3 * id1;
            }
        }
    }
    __syncthreads();

    // epilogue: y = gamma * (Wo @ O + bo) + x
    const float gam = gamma[0];
    for (int idx = tid; idx < CCH * QB; idx += 256) {
        int c = idx >> 6, q = idx & 63;
        const float* wr = sWo + c * ICH;
        const float* ov = sO + q * 17;
        float acc = 0.f;
        #pragma unroll
        for (int i = 0; i < ICH; i++) acc = fmaf(wr[i], ov[i], acc);
        size_t gi = ((size_t)(b * CCH + c)) * NP + (q0 + q);
        y[gi] = gam * (acc + sbo[c]) + x[gi];
    }
}

extern "C" void kernel_launch(void* const* d_in, const int* in_sizes, int n_in,
                              void* d_out, int out_size) {
    const float* x     = (const float*)d_in[0];
    const float* Wq    = (const float*)d_in[1];
    const float* bq    = (const float*)d_in[2];
    const float* Wk    = (const float*)d_in[3];
    const float* bk    = (const float*)d_in[4];
    const float* Wv    = (const float*)d_in[5];
    const float* bv    = (const float*)d_in[6];
    const float* Wo    = (const float*)d_in[7];
    const float* bo    = (const float*)d_in[8];
    const float* gamma = (const float*)d_in[9];
    float* y = (float*)d_out;

    cudaFuncSetAttribute(attn_kernel, cudaFuncAttributeMaxDynamicSharedMemorySize, SMEM_BYTES);

    qkv_kernel<<<(BATCH * NP) / 256, 256>>>(x, Wq, bq, Wk, bk, Wv, bv);
    attn_kernel<<<BATCH * NQB, 256, SMEM_BYTES>>>(x, Wo, bo, gamma, y);
}